// round 4
// baseline (speedup 1.0000x reference)
#include <cuda_runtime.h>
#include <cuda_bf16.h>
#include <cstdint>

// ---------------------------------------------------------------------------
// Grouped per-filter 3x3 valid conv on int8-valued data with TFLite requant.
//   acc[f,j,k] = sum_{m,n,o} x[f,j+m,k+n,o] * w[f,m,n,o] + bias[f]
//
// Robustness: inputs are identified BY SIZE on the host (ordering-agnostic),
// and element storage dtype (int8 / int32 / float32 / bf16) is sniffed from
// bit patterns on device (values are all small ints -> patterns are
// unambiguous). Math is exact integer dp4a in all modes. Output: float32.
//
// Core: per image row r, thread c computes y[t] = dot64(x[f,r,c,:], w[f,t]),
// t = 0..8 taps (144 dp4a; x from GMEM into registers, w via smem broadcast).
// y rows staged in a 3-row smem ring; epilogue:
//   acc[j,k] = sum_{m,n} y[j+m][k+n][3m+n]   (stride-9 LDS, conflict-free).
// ---------------------------------------------------------------------------

#define F_DIM 64
#define H_DIM 256
#define W_DIM 256
#define CIN   64
#define HO_   254
#define WO_   254
#define TJ    32
#define NBANDS 8

#define MODE_I8   0
#define MODE_I32  1
#define MODE_F32  2
#define MODE_BF16 3

__device__ __forceinline__ int pack4(int b0, int b1, int b2, int b3) {
    return __byte_perm(__byte_perm(b0, b1, 0x0040),
                       __byte_perm(b2, b3, 0x0040), 0x5410);
}

__device__ __forceinline__ bool half_is_smallint(unsigned h) {
    if (h == 0) return true;
    float v = __bfloat162float(__ushort_as_bfloat16((unsigned short)h));
    return isfinite(v) && fabsf(v) <= 128.0f && v == rintf(v) && v != 0.0f;
}

// classify a widened-int8 tensor's storage from its first 64 words
__device__ __forceinline__ int sniff_mode(const int* p) {
    int ci = 0, cf = 0, cb = 0, c8 = 0;
    #pragma unroll 1
    for (int k = 0; k < 64; ++k) {
        int v = p[k];
        if (v == 0) continue;
        if (v >= -128 && v <= 127) { ++ci; continue; }
        float fv = __int_as_float(v);
        if (isfinite(fv) && fabsf(fv) <= 128.0f && fv == rintf(fv) && fv != 0.0f) { ++cf; continue; }
        unsigned u = (unsigned)v;
        if (half_is_smallint(u & 0xFFFFu) && half_is_smallint(u >> 16)) { ++cb; continue; }
        ++c8;
    }
    int best = MODE_I8, bc = c8;
    if (ci > bc) { best = MODE_I32;  bc = ci; }
    if (cf > bc) { best = MODE_F32;  bc = cf; }
    if (cb > bc) { best = MODE_BF16; bc = cb; }
    return best;
}

template<int MODE>
__device__ __forceinline__ void load_row_packed(const char* rowptr, int xp[16]) {
    if (MODE == MODE_I8) {
        const int4* p = (const int4*)rowptr;     // 64 B
        #pragma unroll
        for (int i = 0; i < 4; ++i) {
            int4 v = p[i];
            xp[i * 4 + 0] = v.x; xp[i * 4 + 1] = v.y;
            xp[i * 4 + 2] = v.z; xp[i * 4 + 3] = v.w;
        }
    } else if (MODE == MODE_I32) {
        const int4* p = (const int4*)rowptr;     // 256 B
        #pragma unroll
        for (int i = 0; i < 16; ++i) {
            int4 v = p[i];
            xp[i] = pack4(v.x, v.y, v.z, v.w);
        }
    } else if (MODE == MODE_F32) {
        const float4* p = (const float4*)rowptr; // 256 B
        #pragma unroll
        for (int i = 0; i < 16; ++i) {
            float4 v = p[i];
            xp[i] = pack4(__float2int_rn(v.x), __float2int_rn(v.y),
                          __float2int_rn(v.z), __float2int_rn(v.w));
        }
    } else {                                      // BF16: 128 B
        const uint4* p = (const uint4*)rowptr;
        #pragma unroll
        for (int i = 0; i < 8; ++i) {
            uint4 v = p[i];
            unsigned wd[4] = {v.x, v.y, v.z, v.w};
            #pragma unroll
            for (int q = 0; q < 2; ++q) {
                unsigned w0 = wd[2 * q], w1 = wd[2 * q + 1];
                int c0 = __float2int_rn(__uint_as_float(w0 << 16));
                int c1 = __float2int_rn(__uint_as_float(w0 & 0xFFFF0000u));
                int c2 = __float2int_rn(__uint_as_float(w1 << 16));
                int c3 = __float2int_rn(__uint_as_float(w1 & 0xFFFF0000u));
                xp[i * 2 + q] = pack4(c0, c1, c2, c3);
            }
        }
    }
}

template<int MODE>
__device__ __forceinline__ int load_weight_word(const char* wb, size_t widx) {
    if (MODE == MODE_I8) {
        return ((const int*)wb)[widx];
    } else if (MODE == MODE_I32) {
        int4 v = ((const int4*)wb)[widx];
        return pack4(v.x, v.y, v.z, v.w);
    } else if (MODE == MODE_F32) {
        float4 v = ((const float4*)wb)[widx];
        return pack4(__float2int_rn(v.x), __float2int_rn(v.y),
                     __float2int_rn(v.z), __float2int_rn(v.w));
    } else {
        uint2 v = ((const uint2*)wb)[widx];
        return pack4(__float2int_rn(__uint_as_float(v.x << 16)),
                     __float2int_rn(__uint_as_float(v.x & 0xFFFF0000u)),
                     __float2int_rn(__uint_as_float(v.y << 16)),
                     __float2int_rn(__uint_as_float(v.y & 0xFFFF0000u)));
    }
}

template<int MODE>
__device__ __forceinline__ void run_conv(
    const char* __restrict__ xb, const char* __restrict__ wb,
    float* __restrict__ outv, int L,
    int* __restrict__ ybuf,   // [3][W_DIM][9]
    int* __restrict__ swp,    // [144]
    int f, int j0, int jend, int tid,
    int red, int tsh, int ozp, int bfil)
{
    const int E = (MODE == MODE_I8) ? 1 : (MODE == MODE_BF16) ? 2 : 4;

    if (tid < 144)
        swp[tid] = load_weight_word<MODE>(wb, (size_t)f * 144 + tid);
    __syncthreads();

    const long long rnd = 1LL << (tsh - 1);
    const size_t rowstride = (size_t)W_DIM * CIN * E;
    const char* xcol = xb + (size_t)f * H_DIM * rowstride + (size_t)tid * CIN * E;
    const int rlast = jend + 1;

    for (int r = j0; r <= rlast; ++r) {
        int xp[16];
        load_row_packed<MODE>(xcol + (size_t)r * rowstride, xp);

        int y[9];
        #pragma unroll
        for (int t = 0; t < 9; ++t) {
            const int4 w0 = ((const int4*)swp)[t * 4 + 0];
            const int4 w1 = ((const int4*)swp)[t * 4 + 1];
            const int4 w2 = ((const int4*)swp)[t * 4 + 2];
            const int4 w3 = ((const int4*)swp)[t * 4 + 3];
            int a = 0;
            a = __dp4a(xp[0],  w0.x, a);  a = __dp4a(xp[1],  w0.y, a);
            a = __dp4a(xp[2],  w0.z, a);  a = __dp4a(xp[3],  w0.w, a);
            a = __dp4a(xp[4],  w1.x, a);  a = __dp4a(xp[5],  w1.y, a);
            a = __dp4a(xp[6],  w1.z, a);  a = __dp4a(xp[7],  w1.w, a);
            a = __dp4a(xp[8],  w2.x, a);  a = __dp4a(xp[9],  w2.y, a);
            a = __dp4a(xp[10], w2.z, a);  a = __dp4a(xp[11], w2.w, a);
            a = __dp4a(xp[12], w3.x, a);  a = __dp4a(xp[13], w3.y, a);
            a = __dp4a(xp[14], w3.z, a);  a = __dp4a(xp[15], w3.w, a);
            y[t] = a;
        }

        __syncthreads();   // previous epilogue done reading ring slot r%3
        {
            int* yb = ybuf + ((r % 3) * W_DIM + tid) * 9;
            #pragma unroll
            for (int t = 0; t < 9; ++t) yb[t] = y[t];
        }
        __syncthreads();

        if (r >= j0 + 2 && tid < WO_) {
            const int j = r - 2;
            int acc = bfil;
            #pragma unroll
            for (int m = 0; m < 3; ++m) {
                const int* row = ybuf + ((j + m) % 3) * W_DIM * 9;
                #pragma unroll
                for (int n = 0; n < 3; ++n)
                    acc += row[(tid + n) * 9 + (3 * m + n)];
            }
            long long a64 = (long long)acc * (long long)red + rnd;
            int res = (int)(a64 >> tsh) + ozp;
            res = res < -128 ? -128 : (res > 127 ? 127 : res);
            size_t oidx = ((size_t)(f * HO_ + j) * WO_ + tid) * (size_t)L;
            for (int l = 0; l < L; ++l) outv[oidx + l] = (float)res;
        }
    }
}

__global__ void __launch_bounds__(256)
conv2d_grouped_any(const void* __restrict__ x, const void* __restrict__ w,
                   const void* __restrict__ bias,
                   const void* __restrict__ s0, const void* __restrict__ s1,
                   const void* __restrict__ s2,
                   float* __restrict__ out, int L)
{
    __shared__ int ybuf[3 * W_DIM * 9];
    __shared__ __align__(16) int swp[144];

    const int band = blockIdx.x;
    const int f    = blockIdx.y;
    const int tid  = threadIdx.x;

    // ---- storage dtype of x (and w, assumed same) ----
    const int mode = sniff_mode((const int*)x);

    // ---- scalars: {q_mantissa, exponent, output_zero_point} in some order.
    // q_mantissa is huge; exponent precedes output_zero_point in both
    // insertion and alphabetical orderings.
    int qm, expv, ozp;
    {
        int wv[3] = { ((const int*)s0)[0], ((const int*)s1)[0], ((const int*)s2)[0] };
        // try int32 storage
        int nh = 0, hi = -1;
        #pragma unroll
        for (int i = 0; i < 3; ++i)
            if (wv[i] > 100000 || wv[i] < -100000) { ++nh; hi = i; }
        if (nh == 1 && wv[hi] > 0) {
            qm = wv[hi];
            int a = -1, b = -1;
            #pragma unroll
            for (int i = 0; i < 3; ++i) if (i != hi) { if (a < 0) a = i; else b = i; }
            expv = wv[a]; ozp = wv[b];
        } else {
            // try float32 storage
            float fv[3] = { __int_as_float(wv[0]), __int_as_float(wv[1]), __int_as_float(wv[2]) };
            int nh2 = 0, hi2 = -1;
            #pragma unroll
            for (int i = 0; i < 3; ++i)
                if (isfinite(fv[i]) && fabsf(fv[i]) > 100000.0f) { ++nh2; hi2 = i; }
            if (nh2 == 1 && fv[hi2] > 0.0f) {
                qm = (int)(long long)fv[hi2];
                int a = -1, b = -1;
                #pragma unroll
                for (int i = 0; i < 3; ++i) if (i != hi2) { if (a < 0) a = i; else b = i; }
                expv = (int)fv[a]; ozp = (int)fv[b];
            } else {
                // bf16 fallback (low half of each word)
                float bv[3];
                #pragma unroll
                for (int i = 0; i < 3; ++i)
                    bv[i] = __bfloat162float(__ushort_as_bfloat16((unsigned short)(wv[i] & 0xFFFF)));
                int hi3 = 0;
                #pragma unroll
                for (int i = 1; i < 3; ++i) if (fabsf(bv[i]) > fabsf(bv[hi3])) hi3 = i;
                qm = (int)(long long)bv[hi3];
                int a = -1, b = -1;
                #pragma unroll
                for (int i = 0; i < 3; ++i) if (i != hi3) { if (a < 0) a = i; else b = i; }
                expv = (int)bv[a]; ozp = (int)bv[b];
            }
        }
    }
    const int red = (qm < 2147418112) ? ((qm + (1 << 15)) >> 16) : 32767;
    const int tsh = 15 - expv;

    // ---- bias[f] (int32 / float32 / bf16 storage) ----
    int bfil;
    {
        const int* bw = (const int*)bias;
        int bmode = MODE_I32;
        #pragma unroll 1
        for (int k = 0; k < 8; ++k) {
            int v = bw[k];
            if (v == 0) continue;
            if (v >= -4096 && v <= 4096) { bmode = MODE_I32; break; }
            float fv = __int_as_float(v);
            if (isfinite(fv) && fabsf(fv) <= 4096.0f && fv == rintf(fv)) { bmode = MODE_F32; break; }
            bmode = MODE_BF16; break;
        }
        if (bmode == MODE_I32)      bfil = bw[f];
        else if (bmode == MODE_F32) bfil = (int)__int_as_float(bw[f]);
        else bfil = (int)__bfloat162float(((const __nv_bfloat16*)bias)[f]);
    }

    const int j0   = band * TJ;
    const int jend = (j0 + TJ < HO_) ? (j0 + TJ) : HO_;

    if (mode == MODE_I8)
        run_conv<MODE_I8 >((const char*)x, (const char*)w, out, L, ybuf, swp, f, j0, jend, tid, red, tsh, ozp, bfil);
    else if (mode == MODE_I32)
        run_conv<MODE_I32>((const char*)x, (const char*)w, out, L, ybuf, swp, f, j0, jend, tid, red, tsh, ozp, bfil);
    else if (mode == MODE_F32)
        run_conv<MODE_F32>((const char*)x, (const char*)w, out, L, ybuf, swp, f, j0, jend, tid, red, tsh, ozp, bfil);
    else
        run_conv<MODE_BF16>((const char*)x, (const char*)w, out, L, ybuf, swp, f, j0, jend, tid, red, tsh, ozp, bfil);
}

// ---------------------------------------------------------------------------

extern "C" void kernel_launch(void* const* d_in, const int* in_sizes, int n_in,
                              void* d_out, int out_size)
{
    // Identify inputs BY SIZE (ordering-agnostic):
    //   x: 64*256*256*64 = 268435456, w: 64*3*3*64 = 36864, bias: 64,
    //   scalars: three size-1 tensors (kept in their relative order).
    const void* x = nullptr; const void* w = nullptr; const void* b = nullptr;
    const void* s[3] = {nullptr, nullptr, nullptr};
    int ns = 0;
    int ximax = 0;
    for (int i = 1; i < n_in; ++i)
        if (in_sizes[i] > in_sizes[ximax]) ximax = i;
    for (int i = 0; i < n_in; ++i) {
        if (i == ximax)                 x = d_in[i];
        else if (in_sizes[i] == 36864) w = d_in[i];
        else if (in_sizes[i] == 64)    b = d_in[i];
        else if (in_sizes[i] == 1 && ns < 3) s[ns++] = d_in[i];
    }
    // fallback to declared order if anything missing
    if (!x || !w || !b || ns < 3) {
        x = d_in[0]; w = d_in[1]; b = d_in[2];
        s[0] = d_in[3]; s[1] = d_in[4]; s[2] = d_in[5];
    }

    int L = out_size / (F_DIM * HO_ * WO_);
    if (L < 1) L = 1;

    dim3 grid(NBANDS, F_DIM);
    conv2d_grouped_any<<<grid, 256>>>(x, w, b, s[0], s[1], s[2],
                                      (float*)d_out, L);
}

// round 5
// speedup vs baseline: 1.1803x; 1.1803x over previous
#include <cuda_runtime.h>
#include <cuda_bf16.h>
#include <cstdint>

// ---------------------------------------------------------------------------
// Grouped per-filter 3x3 valid conv on int8-valued data with TFLite requant.
//   acc[f,j,k] = sum_{m,n,o} x[f,j+m,k+n,o] * w[f,m,n,o] + bias[f]
//
// Two-phase: a prep kernel sniffs the storage dtype (int8/int32/f32/bf16),
// decodes requant scalars, converts bias, and pre-packs all weights into
// __device__ globals. Then ONE of four mode-specialized conv kernels runs
// (others early-exit on g_mode) -> low register count, 3 CTAs/SM, row
// double-buffering to hide DRAM latency. Exact integer dp4a math throughout.
// ---------------------------------------------------------------------------

#define F_DIM 64
#define H_DIM 256
#define W_DIM 256
#define CIN   64
#define HO_   254
#define WO_   254
#define TJ    16
#define NBANDS 16

#define MODE_I8   0
#define MODE_I32  1
#define MODE_F32  2
#define MODE_BF16 3

__device__ int g_mode, g_red, g_tsh, g_ozp;
__device__ int g_bias[F_DIM];
__device__ int g_wpack[F_DIM * 144];

__device__ __forceinline__ int pack4(int b0, int b1, int b2, int b3) {
    return __byte_perm(__byte_perm(b0, b1, 0x0040),
                       __byte_perm(b2, b3, 0x0040), 0x5410);
}

__device__ __forceinline__ bool half_is_smallint(unsigned h) {
    if (h == 0) return true;
    float v = __bfloat162float(__ushort_as_bfloat16((unsigned short)h));
    return isfinite(v) && fabsf(v) <= 128.0f && v == rintf(v) && v != 0.0f;
}

__device__ __forceinline__ int sniff_mode(const int* p) {
    int ci = 0, cf = 0, cb = 0, c8 = 0;
    #pragma unroll 1
    for (int k = 0; k < 64; ++k) {
        int v = p[k];
        if (v == 0) continue;
        if (v >= -128 && v <= 127) { ++ci; continue; }
        float fv = __int_as_float(v);
        if (isfinite(fv) && fabsf(fv) <= 128.0f && fv == rintf(fv) && fv != 0.0f) { ++cf; continue; }
        unsigned u = (unsigned)v;
        if (half_is_smallint(u & 0xFFFFu) && half_is_smallint(u >> 16)) { ++cb; continue; }
        ++c8;
    }
    int best = MODE_I8, bc = c8;
    if (ci > bc) { best = MODE_I32;  bc = ci; }
    if (cf > bc) { best = MODE_F32;  bc = cf; }
    if (cb > bc) { best = MODE_BF16; bc = cb; }
    return best;
}

// ---------------------------------------------------------------------------
// Prep kernel: mode sniff + scalar decode + bias convert + weight pre-pack.
// ---------------------------------------------------------------------------
__global__ void prep_kernel(const int* __restrict__ x, const char* __restrict__ w,
                            const int* __restrict__ bias,
                            const int* __restrict__ s0, const int* __restrict__ s1,
                            const int* __restrict__ s2)
{
    __shared__ int s_mode, s_bmode;
    const int tid = threadIdx.x;

    if (tid == 0) {
        const int mode = sniff_mode(x);
        g_mode = mode; s_mode = mode;

        // scalars {q_mantissa, exponent, output_zero_point} in some order;
        // q_mantissa is huge and positive; exponent precedes ozp in both
        // insertion and alphabetical orderings.
        int qm, expv, ozp;
        int wv[3] = { s0[0], s1[0], s2[0] };
        int nh = 0, hi = -1;
        for (int i = 0; i < 3; ++i)
            if (wv[i] > 100000 || wv[i] < -100000) { ++nh; hi = i; }
        if (nh == 1 && wv[hi] > 0) {
            qm = wv[hi];
            int a = -1, b = -1;
            for (int i = 0; i < 3; ++i) if (i != hi) { if (a < 0) a = i; else b = i; }
            expv = wv[a]; ozp = wv[b];
        } else {
            float fv[3] = { __int_as_float(wv[0]), __int_as_float(wv[1]), __int_as_float(wv[2]) };
            int nh2 = 0, hi2 = -1;
            for (int i = 0; i < 3; ++i)
                if (isfinite(fv[i]) && fabsf(fv[i]) > 100000.0f) { ++nh2; hi2 = i; }
            if (nh2 == 1 && fv[hi2] > 0.0f) {
                qm = (int)(long long)fv[hi2];
                int a = -1, b = -1;
                for (int i = 0; i < 3; ++i) if (i != hi2) { if (a < 0) a = i; else b = i; }
                expv = (int)fv[a]; ozp = (int)fv[b];
            } else {
                float bv[3];
                for (int i = 0; i < 3; ++i)
                    bv[i] = __bfloat162float(__ushort_as_bfloat16((unsigned short)(wv[i] & 0xFFFF)));
                int hi3 = 0;
                for (int i = 1; i < 3; ++i) if (fabsf(bv[i]) > fabsf(bv[hi3])) hi3 = i;
                qm = (int)(long long)bv[hi3];
                int a = -1, b = -1;
                for (int i = 0; i < 3; ++i) if (i != hi3) { if (a < 0) a = i; else b = i; }
                expv = (int)bv[a]; ozp = (int)bv[b];
            }
        }
        g_red = (qm < 2147418112) ? ((qm + (1 << 15)) >> 16) : 32767;
        g_tsh = 15 - expv;
        g_ozp = ozp;

        // bias storage mode
        int bm = MODE_I32;
        for (int k = 0; k < 8; ++k) {
            int v = bias[k];
            if (v == 0) continue;
            if (v >= -4096 && v <= 4096) { bm = MODE_I32; break; }
            float fvb = __int_as_float(v);
            if (isfinite(fvb) && fabsf(fvb) <= 4096.0f && fvb == rintf(fvb)) { bm = MODE_F32; break; }
            bm = MODE_BF16; break;
        }
        s_bmode = bm;
    }
    __syncthreads();
    const int mode = s_mode, bmode = s_bmode;

    if (tid < F_DIM) {
        if (bmode == MODE_I32)      g_bias[tid] = bias[tid];
        else if (bmode == MODE_F32) g_bias[tid] = (int)__int_as_float(bias[tid]);
        else g_bias[tid] = (int)__bfloat162float(((const __nv_bfloat16*)bias)[tid]);
    }

    for (int i = tid; i < F_DIM * 144; i += blockDim.x) {
        int pw;
        if (mode == MODE_I8) {
            pw = ((const int*)w)[i];
        } else if (mode == MODE_I32) {
            int4 v = ((const int4*)w)[i];
            pw = pack4(v.x, v.y, v.z, v.w);
        } else if (mode == MODE_F32) {
            float4 v = ((const float4*)w)[i];
            pw = pack4(__float2int_rn(v.x), __float2int_rn(v.y),
                       __float2int_rn(v.z), __float2int_rn(v.w));
        } else {
            uint2 v = ((const uint2*)w)[i];
            pw = pack4(__float2int_rn(__uint_as_float(v.x << 16)),
                       __float2int_rn(__uint_as_float(v.x & 0xFFFF0000u)),
                       __float2int_rn(__uint_as_float(v.y << 16)),
                       __float2int_rn(__uint_as_float(v.y & 0xFFFF0000u)));
        }
        g_wpack[i] = pw;
    }
}

// ---------------------------------------------------------------------------

template<int MODE>
__device__ __forceinline__ void load_row_packed(const char* rowptr, int xp[16]) {
    if (MODE == MODE_I8) {
        const int4* p = (const int4*)rowptr;     // 64 B
        #pragma unroll
        for (int i = 0; i < 4; ++i) {
            int4 v = p[i];
            xp[i * 4 + 0] = v.x; xp[i * 4 + 1] = v.y;
            xp[i * 4 + 2] = v.z; xp[i * 4 + 3] = v.w;
        }
    } else if (MODE == MODE_I32) {
        const int4* p = (const int4*)rowptr;     // 256 B
        #pragma unroll
        for (int i = 0; i < 16; ++i) {
            int4 v = p[i];
            xp[i] = pack4(v.x, v.y, v.z, v.w);
        }
    } else if (MODE == MODE_F32) {
        const float4* p = (const float4*)rowptr; // 256 B
        #pragma unroll
        for (int i = 0; i < 16; ++i) {
            float4 v = p[i];
            xp[i] = pack4(__float2int_rn(v.x), __float2int_rn(v.y),
                          __float2int_rn(v.z), __float2int_rn(v.w));
        }
    } else {                                      // BF16: 128 B
        const uint4* p = (const uint4*)rowptr;
        #pragma unroll
        for (int i = 0; i < 8; ++i) {
            uint4 v = p[i];
            unsigned wd[4] = {v.x, v.y, v.z, v.w};
            #pragma unroll
            for (int q = 0; q < 2; ++q) {
                unsigned w0 = wd[2 * q], w1 = wd[2 * q + 1];
                int c0 = __float2int_rn(__uint_as_float(w0 << 16));
                int c1 = __float2int_rn(__uint_as_float(w0 & 0xFFFF0000u));
                int c2 = __float2int_rn(__uint_as_float(w1 << 16));
                int c3 = __float2int_rn(__uint_as_float(w1 & 0xFFFF0000u));
                xp[i * 2 + q] = pack4(c0, c1, c2, c3);
            }
        }
    }
}

template<int MODE>
__global__ void __launch_bounds__(256, 3)
conv_main(const char* __restrict__ xb, float* __restrict__ outv, int L)
{
    if (g_mode != MODE) return;

    __shared__ int ybuf[3 * W_DIM * 9];
    __shared__ __align__(16) int swp[144];

    const int band = blockIdx.x;
    const int f    = blockIdx.y;
    const int tid  = threadIdx.x;

    if (tid < 144) swp[tid] = g_wpack[f * 144 + tid];

    const int red  = g_red;
    const int tsh  = g_tsh;
    const int ozp  = g_ozp;
    const int bfil = g_bias[f];
    const long long rnd = 1LL << (tsh - 1);

    const int j0    = band * TJ;
    const int jend  = (j0 + TJ < HO_) ? (j0 + TJ) : HO_;  // exclusive
    const int rlast = jend + 1;

    const int E = (MODE == MODE_I8) ? 1 : (MODE == MODE_BF16) ? 2 : 4;
    const size_t rs = (size_t)W_DIM * CIN * E;
    const char* xcol = xb + (size_t)f * H_DIM * rs + (size_t)tid * CIN * E;

    int xc[16], xn[16];
    load_row_packed<MODE>(xcol + (size_t)j0 * rs, xc);
    __syncthreads();   // weights visible

    for (int r = j0; r <= rlast; ++r) {
        // prefetch next row: loads in flight while dp4a on current row runs
        if (r < rlast)
            load_row_packed<MODE>(xcol + (size_t)(r + 1) * rs, xn);

        int y[9];
        #pragma unroll
        for (int t = 0; t < 9; ++t) {
            const int4 w0 = ((const int4*)swp)[t * 4 + 0];
            const int4 w1 = ((const int4*)swp)[t * 4 + 1];
            const int4 w2 = ((const int4*)swp)[t * 4 + 2];
            const int4 w3 = ((const int4*)swp)[t * 4 + 3];
            int a = 0;
            a = __dp4a(xc[0],  w0.x, a);  a = __dp4a(xc[1],  w0.y, a);
            a = __dp4a(xc[2],  w0.z, a);  a = __dp4a(xc[3],  w0.w, a);
            a = __dp4a(xc[4],  w1.x, a);  a = __dp4a(xc[5],  w1.y, a);
            a = __dp4a(xc[6],  w1.z, a);  a = __dp4a(xc[7],  w1.w, a);
            a = __dp4a(xc[8],  w2.x, a);  a = __dp4a(xc[9],  w2.y, a);
            a = __dp4a(xc[10], w2.z, a);  a = __dp4a(xc[11], w2.w, a);
            a = __dp4a(xc[12], w3.x, a);  a = __dp4a(xc[13], w3.y, a);
            a = __dp4a(xc[14], w3.z, a);  a = __dp4a(xc[15], w3.w, a);
            y[t] = a;
        }

        __syncthreads();   // previous epilogue done reading ring slot r%3
        {
            int* yb = ybuf + ((r % 3) * W_DIM + tid) * 9;
            #pragma unroll
            for (int t = 0; t < 9; ++t) yb[t] = y[t];
        }
        __syncthreads();

        if (r >= j0 + 2 && tid < WO_) {
            const int j = r - 2;
            int acc = bfil;
            #pragma unroll
            for (int m = 0; m < 3; ++m) {
                const int* row = ybuf + ((j + m) % 3) * W_DIM * 9;
                #pragma unroll
                for (int n = 0; n < 3; ++n)
                    acc += row[(tid + n) * 9 + (3 * m + n)];
            }
            long long a64 = (long long)acc * (long long)red + rnd;
            int res = (int)(a64 >> tsh) + ozp;
            res = res < -128 ? -128 : (res > 127 ? 127 : res);
            size_t oidx = ((size_t)(f * HO_ + j) * WO_ + tid) * (size_t)L;
            for (int l = 0; l < L; ++l) outv[oidx + l] = (float)res;
        }

        #pragma unroll
        for (int i = 0; i < 16; ++i) xc[i] = xn[i];
    }
}

// ---------------------------------------------------------------------------

extern "C" void kernel_launch(void* const* d_in, const int* in_sizes, int n_in,
                              void* d_out, int out_size)
{
    // Identify inputs BY SIZE (ordering-agnostic):
    //   x = largest, w = 36864 elements, bias = 64, scalars = three size-1.
    const void* x = nullptr; const void* w = nullptr; const void* b = nullptr;
    const void* s[3] = {nullptr, nullptr, nullptr};
    int ns = 0;
    int ximax = 0;
    for (int i = 1; i < n_in; ++i)
        if (in_sizes[i] > in_sizes[ximax]) ximax = i;
    for (int i = 0; i < n_in; ++i) {
        if (i == ximax)                 x = d_in[i];
        else if (in_sizes[i] == 36864) w = d_in[i];
        else if (in_sizes[i] == 64)    b = d_in[i];
        else if (in_sizes[i] == 1 && ns < 3) s[ns++] = d_in[i];
    }
    if (!x || !w || !b || ns < 3) {
        x = d_in[0]; w = d_in[1]; b = d_in[2];
        s[0] = d_in[3]; s[1] = d_in[4]; s[2] = d_in[5];
    }

    int L = out_size / (F_DIM * HO_ * WO_);
    if (L < 1) L = 1;

    prep_kernel<<<1, 256>>>((const int*)x, (const char*)w, (const int*)b,
                            (const int*)s[0], (const int*)s[1], (const int*)s[2]);

    dim3 grid(NBANDS, F_DIM);
    conv_main<MODE_I8  ><<<grid, 256>>>((const char*)x, (float*)d_out, L);
    conv_main<MODE_I32 ><<<grid, 256>>>((const char*)x, (float*)d_out, L);
    conv_main<MODE_F32 ><<<grid, 256>>>((const char*)x, (float*)d_out, L);
    conv_main<MODE_BF16><<<grid, 256>>>((const char*)x, (float*)d_out, L);
}